// round 17
// baseline (speedup 1.0000x reference)
#include <cuda_runtime.h>
#include <cuda_fp16.h>
#include <cstdint>

// SimpleGNNBlock: out[b,k] = sum_p relu( relu(feats[b,p,:] @ W1 + b1) @ W2 + b2 )
// feats = [dx, dy, 1/sqrt(dx^2+dy^2+1e-6), m_p],  B=32768, P=128, H=64.
//
// R17: R15 (transposed layer 2, vectorized h layout, LDS.128/STS.128) with
// the layer-2 warp tile widened to 32 k-cols x 32 p-rows: h-row read
// replication drops 4x -> 2x (layer-2 LDS wavefronts halve). A-frags grow to
// 32 regs; compensated by moving W1 fragments to smem (-16 regs). Peak live
// set ~75 regs -> still 3 CTAs/SM.

#define BATCHES 32768
#define PP 128
#define HH 64
#define GRID 4096
#define BPC (BATCHES / GRID)    // 8
#define HW 36                   // h row stride in words (= 9 uint4)

__device__ __forceinline__ uint32_t f2tf32(float x) {
    uint32_t u;
    asm("cvt.rna.tf32.f32 %0, %1;" : "=r"(u) : "f"(x));
    return u;
}
// pack two fp32 -> f16x2 {lo, hi}
__device__ __forceinline__ uint32_t pack_f16(float lo, float hi) {
    uint32_t u;
    asm("cvt.rn.f16x2.f32 %0, %1, %2;" : "=r"(u) : "f"(hi), "f"(lo));
    return u;
}

__global__ __launch_bounds__(256, 3)
void gnn_kernel(const float* __restrict__ planet_xy,   // (B,P,2)
                const float* __restrict__ planet_m,    // (P)
                const float* __restrict__ ast_xy,      // (B,2)
                const float* __restrict__ W1,          // (4,H)
                const float* __restrict__ b1,          // (H)
                const float* __restrict__ W2,          // (H,H) [j][k]
                const float* __restrict__ b2,          // (H)
                float* __restrict__ out)               // (B,H)
{
    __shared__ __align__(16) uint32_t h2[128 * HW];  // h fp16x2, permuted words
    __shared__ uint4 feats_s[PP];                    // tf32 bits {dx,dy,inv,m}
    __shared__ uint2 w1s[256];                       // W1 frags [n][lane]={b0,bias}
    __shared__ float sacc[4][HH];                    // per-ph4 partial banks

    const int tid  = threadIdx.x;
    const int lane = tid & 31;
    const int w    = tid >> 5;     // warp 0..7
    const int g    = lane >> 2;    // group 0..7
    const int t    = lane & 3;     // thread-in-group 0..3
    const int wk2  = w & 1;        // output-k half: k = wk2*32 .. +31 (2 m-tiles)
    const int ph4  = w >> 1;       // p-quarter: p = ph4*32 .. +31 (4 n-tiles)

    uint4* h4 = reinterpret_cast<uint4*>(h2);        // row stride 9 uint4

    // ---- layer-2 A-fragments = W2^T (m16n8k16 row A), 2 m-tiles, 32 regs ----
    uint32_t af[2][4][4];
    float bk[2][2];
    #pragma unroll
    for (int mt = 0; mt < 2; ++mt) {
        const int m0 = wk2 * 32 + mt * 16;
        #pragma unroll
        for (int kt = 0; kt < 4; ++kt) {
            const int j0 = kt * 16;
            af[mt][kt][0] = pack_f16(W2[(j0 + 2 * t)     * HH + m0 + g],
                                     W2[(j0 + 2 * t + 1) * HH + m0 + g]);
            af[mt][kt][1] = pack_f16(W2[(j0 + 2 * t)     * HH + m0 + g + 8],
                                     W2[(j0 + 2 * t + 1) * HH + m0 + g + 8]);
            af[mt][kt][2] = pack_f16(W2[(j0 + 2 * t + 8) * HH + m0 + g],
                                     W2[(j0 + 2 * t + 9) * HH + m0 + g]);
            af[mt][kt][3] = pack_f16(W2[(j0 + 2 * t + 8) * HH + m0 + g + 8],
                                     W2[(j0 + 2 * t + 9) * HH + m0 + g + 8]);
        }
        bk[mt][0] = b2[m0 + g];
        bk[mt][1] = b2[m0 + g + 8];
    }

    // ---- W1 tf32 fragments -> smem (entry n = tid>>5, lane = tid&31) ----
    {
        int n = tid >> 5, l = tid & 31;
        int gg = l >> 2, tt = l & 3;
        int col = n * 8 + gg;
        w1s[tid] = make_uint2(f2tf32(W1[tt * HH + col]),
                              (tt == 0) ? f2tf32(b1[col]) : 0u);
    }
    const uint32_t a1pad = (t == 0) ? 0x3f800000u : 0u;   // tf32 1.0 bias col

    uint32_t m32 = 0;
    if (tid < PP) m32 = f2tf32(planet_m[tid]);
    __syncthreads();

    for (int it = 0; it < BPC; ++it) {
        const int b = blockIdx.x + it * GRID;

        // ---- feats (tf32 bits), one thread per p ----
        if (tid < PP) {
            float2 pxy = reinterpret_cast<const float2*>(planet_xy)[b * PP + tid];
            float ax = ast_xy[2 * b], ay = ast_xy[2 * b + 1];
            float dx = pxy.x - ax;
            float dy = pxy.y - ay;
            float inv = rsqrtf(fmaf(dx, dx, fmaf(dy, dy, 1e-6f)));
            feats_s[tid] = make_uint4(f2tf32(dx), f2tf32(dy), f2tf32(inv), m32);
        }
        __syncthreads();

        // ---- layer 1: warp w owns p-rows w*16..+15, all 8 col-tiles ----
        {
            const uint32_t* fu = reinterpret_cast<const uint32_t*>(feats_s);
            uint32_t a0 = fu[(w * 16 + g)     * 4 + t];
            uint32_t a1 = fu[(w * 16 + g + 8) * 4 + t];
            uint32_t pk[8], qk[8];
            #pragma unroll
            for (int n = 0; n < 8; ++n) {
                uint2 wf = w1s[n * 32 + lane];
                float c0 = 0.f, c1 = 0.f, c2 = 0.f, c3 = 0.f;
                asm volatile(
                    "mma.sync.aligned.m16n8k8.row.col.f32.tf32.tf32.f32 "
                    "{%0,%1,%2,%3}, {%4,%5,%6,%7}, {%8,%9}, {%0,%1,%2,%3};"
                    : "+f"(c0), "+f"(c1), "+f"(c2), "+f"(c3)
                    : "r"(a0), "r"(a1), "r"(a1pad), "r"(a1pad),
                      "r"(wf.x), "r"(wf.y));
                pk[n] = pack_f16(fmaxf(c0, 0.f), fmaxf(c1, 0.f));  // row g
                qk[n] = pack_f16(fmaxf(c2, 0.f), fmaxf(c3, 0.f));  // row g+8
            }
            const int r0 = w * 16 + g;
            h4[r0 * 9 + 2 * t]           = make_uint4(pk[0], pk[1], pk[2], pk[3]);
            h4[r0 * 9 + 2 * t + 1]       = make_uint4(pk[4], pk[5], pk[6], pk[7]);
            h4[(r0 + 8) * 9 + 2 * t]     = make_uint4(qk[0], qk[1], qk[2], qk[3]);
            h4[(r0 + 8) * 9 + 2 * t + 1] = make_uint4(qk[4], qk[5], qk[6], qk[7]);
        }
        __syncthreads();

        // ---- layer 2 transposed: warp (wk2, ph4): k in wk2*32..+31,
        //      p in ph4*32..+31 (4 n-tiles). B loaded once per nt, used by
        //      both m-tiles -> h read replication 2x. ----
        float s[2][2] = {{0.f, 0.f}, {0.f, 0.f}};
        #pragma unroll
        for (int nt = 0; nt < 4; ++nt) {
            const int p0 = ph4 * 32 + nt * 8;
            uint4 B0 = h4[(p0 + g) * 9 + 2 * t];       // kt0/kt1 frag words
            uint4 B1 = h4[(p0 + g) * 9 + 2 * t + 1];   // kt2/kt3
            #pragma unroll
            for (int mt = 0; mt < 2; ++mt) {
                float c0 = 0.f, c1 = 0.f, c2 = 0.f, c3 = 0.f;
                #pragma unroll
                for (int kt = 0; kt < 4; ++kt) {
                    uint32_t bb0 = (kt == 0) ? B0.x : (kt == 1) ? B0.z : (kt == 2) ? B1.x : B1.z;
                    uint32_t bb1 = (kt == 0) ? B0.y : (kt == 1) ? B0.w : (kt == 2) ? B1.y : B1.w;
                    asm volatile(
                        "mma.sync.aligned.m16n8k16.row.col.f32.f16.f16.f32 "
                        "{%0,%1,%2,%3}, {%4,%5,%6,%7}, {%8,%9}, {%0,%1,%2,%3};"
                        : "+f"(c0), "+f"(c1), "+f"(c2), "+f"(c3)
                        : "r"(af[mt][kt][0]), "r"(af[mt][kt][1]),
                          "r"(af[mt][kt][2]), "r"(af[mt][kt][3]),
                          "r"(bb0), "r"(bb1));
                }
                s[mt][0] += fmaxf(c0 + bk[mt][0], 0.f) + fmaxf(c1 + bk[mt][0], 0.f);
                s[mt][1] += fmaxf(c2 + bk[mt][1], 0.f) + fmaxf(c3 + bk[mt][1], 0.f);
            }
        }

        // ---- reduce over p: shuffle over t, STS into per-ph4 bank ----
        #pragma unroll
        for (int mt = 0; mt < 2; ++mt) {
            float v0 = s[mt][0], v1 = s[mt][1];
            v0 += __shfl_xor_sync(0xffffffffu, v0, 1);
            v1 += __shfl_xor_sync(0xffffffffu, v1, 1);
            v0 += __shfl_xor_sync(0xffffffffu, v0, 2);
            v1 += __shfl_xor_sync(0xffffffffu, v1, 2);
            if (t == 0) {
                int k0 = wk2 * 32 + mt * 16 + g;
                sacc[ph4][k0]     = v0;
                sacc[ph4][k0 + 8] = v1;
            }
        }
        __syncthreads();

        if (tid < HH)
            out[b * HH + tid] = (sacc[0][tid] + sacc[1][tid])
                              + (sacc[2][tid] + sacc[3][tid]);
        // next-iter post-feats barrier orders this read before new sacc STS
    }
}

extern "C" void kernel_launch(void* const* d_in, const int* in_sizes, int n_in,
                              void* d_out, int out_size) {
    (void)in_sizes; (void)n_in; (void)out_size;
    const float* planet_xy = (const float*)d_in[0];
    const float* planet_m  = (const float*)d_in[1];
    const float* ast_xy    = (const float*)d_in[2];
    const float* W1        = (const float*)d_in[3];
    const float* b1        = (const float*)d_in[4];
    const float* W2        = (const float*)d_in[5];
    const float* b2        = (const float*)d_in[6];
    float* out             = (float*)d_out;

    gnn_kernel<<<GRID, 256>>>(planet_xy, planet_m, ast_xy, W1, b1, W2, b2, out);
}